// round 13
// baseline (speedup 1.0000x reference)
#include <cuda_runtime.h>
#include <cuda_fp16.h>
#include <cstdint>

#define Bb 32
#define Ss 2048
#define Hh 512
#define Ee 512
#define NROWS (Bb*Ss)

#define NFULL 444                     // full M=128 tiles (= 3*148)
#define NHALF 136                     // half M=64 tiles at grid end (LPT)
#define ROWS_FULL (NFULL*128)         // 56832

// ---- device scratch ----
__device__ __half g_Wh[Hh*Hh];
__device__ float  g_dvpart[8*Bb*Hh];
__device__ float  g_wcpart[16*Hh];
__device__ float  g_att[NROWS];
__device__ int    g_done[Bb];         // zero-init; self-resetting

// ---- GEMM geometry ----
#define AS_STRIDE 520
#define BS_STRIDE 72
#define AS_BYTES (128*AS_STRIDE*2)    // 133120
#define BS_BYTES (128*BS_STRIDE*2)    // 18432
#define NSTAGE 4
#define OFF_BS   AS_BYTES
#define OFF_DVEC (OFF_BS + NSTAGE*BS_BYTES)   // 206848
#define OFF_WC   (OFF_DVEC + 2048)
#define OFF_VW   (OFF_WC + 2048)
#define OFF_COV  (OFF_VW + 2048)
#define OFF_HALF (OFF_COV + 512)
#define SMEM_DYN (OFF_HALF + 4*128*4)         // 215552

__device__ __forceinline__ uint32_t smem_u32(const void* p) {
    uint32_t a;
    asm("{ .reg .u64 t; cvta.to.shared.u64 t, %1; cvt.u32.u64 %0, t; }" : "=r"(a) : "l"(p));
    return a;
}
#define CP16(dst, src) asm volatile("cp.async.cg.shared.global [%0], [%1], 16;" :: "r"(dst), "l"(src))
#define CP_COMMIT()    asm volatile("cp.async.commit_group;" ::: "memory")
#define CP_WAIT2()     asm volatile("cp.async.wait_group 2;" ::: "memory")
#define CP_WAIT0()     asm volatile("cp.async.wait_group 0;" ::: "memory")

#define LDMX4(r0, r1, r2, r3, a) \
    asm volatile("ldmatrix.sync.aligned.m8n8.x4.shared.b16 {%0,%1,%2,%3}, [%4];" \
        : "=r"(r0), "=r"(r1), "=r"(r2), "=r"(r3) : "r"(a))

__device__ __forceinline__ void mma_f16(float* c, const uint32_t* a,
                                        uint32_t b0, uint32_t b1) {
    asm volatile(
        "mma.sync.aligned.m16n8k16.row.col.f32.f16.f16.f32 "
        "{%0,%1,%2,%3}, {%4,%5,%6,%7}, {%8,%9}, {%0,%1,%2,%3};"
        : "+f"(c[0]), "+f"(c[1]), "+f"(c[2]), "+f"(c[3])
        : "r"(a[0]), "r"(a[1]), "r"(a[2]), "r"(a[3]), "r"(b0), "r"(b1));
}

// ---------------------------------------------------------------------------
// prep (528 blocks x 256): unchanged
// ---------------------------------------------------------------------------
__global__ void prep_kernel(const float* __restrict__ dec_input,
                            const float* __restrict__ W) {
    const int blk = blockIdx.x, tid = threadIdx.x;
    if (blk < 256) {
        __shared__ float t[32][33];
        const int bc = blk & 15, br = blk >> 4;
        const int lx = tid & 31, ly = tid >> 5;
        #pragma unroll
        for (int i = 0; i < 4; i++)
            t[ly + 8*i][lx] = W[(size_t)(br*32 + ly + 8*i)*Hh + bc*32 + lx];
        __syncthreads();
        #pragma unroll
        for (int i = 0; i < 4; i++)
            g_Wh[(size_t)(bc*32 + ly + 8*i)*Hh + br*32 + lx] = __float2half_rn(t[lx][ly + 8*i]);
    } else if (blk < 512) {
        const int loc = blk - 256;
        const int b = loc >> 3, ec = loc & 7;
        __shared__ float sdec[64];
        if (tid < 64) sdec[tid] = dec_input[b*Ee + ec*64 + tid];
        __syncthreads();
        const float* Ws = W + (size_t)(Hh + ec*64) * Hh;
        const int h0 = tid, h1 = tid + 256;
        float a0 = 0.f, a1 = 0.f;
        #pragma unroll 8
        for (int e = 0; e < 64; e++) {
            const float d = sdec[e];
            a0 = fmaf(d, Ws[(size_t)e*Hh + h0], a0);
            a1 = fmaf(d, Ws[(size_t)e*Hh + h1], a1);
        }
        g_dvpart[(size_t)(ec*Bb + b)*Hh + h0] = a0;
        g_dvpart[(size_t)(ec*Bb + b)*Hh + h1] = a1;
    } else {
        const int p = blk - 512;
        const float* Wc = W + (size_t)(Hh + Ee + p*32) * Hh;
        const int h0 = tid, h1 = tid + 256;
        float a0 = 0.f, a1 = 0.f;
        #pragma unroll
        for (int r = 0; r < 32; r++) {
            a0 += Wc[(size_t)r*Hh + h0];
            a1 += Wc[(size_t)r*Hh + h1];
        }
        g_wcpart[p*Hh + h0] = a0;
        g_wcpart[p*Hh + h1] = a1;
    }
}

// ---------------------------------------------------------------------------
// GEMM + fused per-batch softmax. 580 CTAs, 512 threads (16 warps = 4M x 4N).
// 4-stage B pipeline, single barrier per iteration.
// ---------------------------------------------------------------------------
__global__ __launch_bounds__(512, 1) void gemm_kernel(
    const float* __restrict__ enc,
    const float* __restrict__ cov,
    const float* __restrict__ v_w,
    const float* __restrict__ bias,
    const int* __restrict__ lens,
    float* __restrict__ out)
{
    extern __shared__ char sm[];
    float* s_dvec = (float*)(sm + OFF_DVEC);
    float* s_wc   = (float*)(sm + OFF_WC);
    float* s_vw   = (float*)(sm + OFF_VW);
    float* s_cov  = (float*)(sm + OFF_COV);
    float* s_half = (float*)(sm + OFF_HALF);   // [4][128]
    __shared__ float s_red[17];
    __shared__ int s_last;

    const uint32_t sb = smem_u32(sm);
    const int tid = threadIdx.x;
    const int wid = tid >> 5, lane = tid & 31;
    const int gid = lane >> 2, qid = lane & 3;
    const int wm = wid >> 2, wn = wid & 3;     // 4 x 4 warp grid

    const int isFull  = (blockIdx.x < NFULL);
    const int MI      = isFull ? 2 : 1;
    const int mrows   = isFull ? 128 : 64;
    const int rowBand = isFull ? 32 : 16;
    const int row0    = isFull ? blockIdx.x * 128
                               : ROWS_FULL + (blockIdx.x - NFULL) * 64;
    const int b = row0 >> 11;

    // B loader: 512 threads, 2x CP16 per chunk
    const int ldr_n  = tid >> 2;
    const int ldr_k0 = (tid & 3) * 16;
    auto issueB = [&](int q) {
        const int nc = q >> 3, kc = q & 7;
        const uint32_t dst = sb + OFF_BS + (q % NSTAGE)*BS_BYTES + ldr_n*(BS_STRIDE*2) + ldr_k0*2;
        const __half* src = g_Wh + (size_t)(nc*128 + ldr_n)*Hh + kc*64 + ldr_k0;
        CP16(dst,      src);
        CP16(dst + 16, src + 8);
    };

    issueB(0); CP_COMMIT();
    issueB(1); CP_COMMIT();
    issueB(2); CP_COMMIT();

    // epilogue constants
    for (int i = tid; i < Hh; i += 512) {
        float dv = bias[i];
        #pragma unroll
        for (int ec = 0; ec < 8; ec++) dv += g_dvpart[(size_t)(ec*Bb + b)*Hh + i];
        s_dvec[i] = dv;
        float w = 0.f;
        #pragma unroll
        for (int p = 0; p < 16; p++) w += g_wcpart[p*Hh + i];
        s_wc[i] = w;
        s_vw[i] = v_w[i];
    }
    if (tid < mrows) s_cov[tid] = cov[row0 + tid];

    // A tile upfront: mrows x 512 fp32 -> fp16 smem
    {
        const float4* encv = (const float4*)(enc + (size_t)row0 * Hh);
        const int nIter = mrows >> 2;
        #pragma unroll 8
        for (int i = 0; i < nIter; i++) {
            int idx = tid + i*512;
            int r = idx >> 7, c4 = idx & 127;
            float4 v = encv[r*128 + c4];
            __half2 h0 = __float22half2_rn(make_float2(v.x, v.y));
            __half2 h1 = __float22half2_rn(make_float2(v.z, v.w));
            char* dst = sm + r*(AS_STRIDE*2) + c4*8;
            *(__half2*)dst = h0;
            *(__half2*)(dst + 4) = h1;
        }
    }

    const uint32_t baseA = sb
        + (uint32_t)(wm*rowBand + ((lane>>3)&1)*8 + (lane&7)) * (AS_STRIDE*2)
        + (uint32_t)((lane>>4)&1) * 16;
    const uint32_t baseBrow = (uint32_t)(wn*32 + ((lane>>4)&1)*8 + (lane&7)) * (BS_STRIDE*2)
        + (uint32_t)((lane>>3)&1) * 16;

    float p[2][2] = {{0.f, 0.f}, {0.f, 0.f}};
    float acc[2][4][4];

    #pragma unroll 1
    for (int q = 0; q < 32; q++) {
        const int nc = q >> 3, kc = q & 7;
        if (kc == 0) {
            #pragma unroll
            for (int mi = 0; mi < 2; mi++)
                #pragma unroll
                for (int j = 0; j < 4; j++)
                    #pragma unroll
                    for (int c = 0; c < 4; c++) acc[mi][j][c] = 0.f;
        }
        if (q < 30) CP_WAIT2(); else CP_WAIT0();
        __syncthreads();

        const uint32_t bsStage = sb + OFF_BS + (q % NSTAGE)*BS_BYTES + baseBrow;

        #pragma unroll
        for (int ks = 0; ks < 4; ks++) {
            uint32_t a[2][4];
            const uint32_t aAddr = baseA + (uint32_t)(kc*64 + ks*16)*2;
            LDMX4(a[0][0], a[0][1], a[0][2], a[0][3], aAddr);
            if (MI == 2)
                LDMX4(a[1][0], a[1][1], a[1][2], a[1][3], aAddr + 16*(AS_STRIDE*2));

            uint32_t bq[2][4];
            const uint32_t bAddr = bsStage + (uint32_t)(ks*16)*2;
            #pragma unroll
            for (int jp = 0; jp < 2; jp++)
                LDMX4(bq[jp][0], bq[jp][1], bq[jp][2], bq[jp][3],
                      bAddr + (uint32_t)jp*16*(BS_STRIDE*2));

            #pragma unroll
            for (int jp = 0; jp < 2; jp++) {
                mma_f16(acc[0][2*jp],   a[0], bq[jp][0], bq[jp][1]);
                mma_f16(acc[0][2*jp+1], a[0], bq[jp][2], bq[jp][3]);
                if (MI == 2) {
                    mma_f16(acc[1][2*jp],   a[1], bq[jp][0], bq[jp][1]);
                    mma_f16(acc[1][2*jp+1], a[1], bq[jp][2], bq[jp][3]);
                }
            }
        }

        if (kc == 7) {
            #pragma unroll
            for (int mi = 0; mi < 2; mi++) {
                if (mi >= MI) break;
                const int r0 = wm*rowBand + mi*16 + gid;
                const float cv0 = s_cov[r0], cv1 = s_cov[r0 + 8];
                #pragma unroll
                for (int j = 0; j < 4; j++) {
                    const int n0 = nc*128 + wn*32 + j*8 + qid*2;
                    const float d0 = s_dvec[n0], d1 = s_dvec[n0+1];
                    const float w0 = s_wc[n0],   w1 = s_wc[n0+1];
                    const float v0 = s_vw[n0],   v1 = s_vw[n0+1];
                    float z, t;
                    z = acc[mi][j][0] + d0 + cv0*w0;
                    asm("tanh.approx.f32 %0, %1;" : "=f"(t) : "f"(z));  p[mi][0] = fmaf(v0, t, p[mi][0]);
                    z = acc[mi][j][1] + d1 + cv0*w1;
                    asm("tanh.approx.f32 %0, %1;" : "=f"(t) : "f"(z));  p[mi][0] = fmaf(v1, t, p[mi][0]);
                    z = acc[mi][j][2] + d0 + cv1*w0;
                    asm("tanh.approx.f32 %0, %1;" : "=f"(t) : "f"(z));  p[mi][1] = fmaf(v0, t, p[mi][1]);
                    z = acc[mi][j][3] + d1 + cv1*w1;
                    asm("tanh.approx.f32 %0, %1;" : "=f"(t) : "f"(z));  p[mi][1] = fmaf(v1, t, p[mi][1]);
                }
            }
        }

        if (q < 29) { issueB(q + 3); CP_COMMIT(); }
    }

    // reduce over qid lanes; combine the 4 wn bands via smem; store logits
    #pragma unroll
    for (int mi = 0; mi < 2; mi++)
        #pragma unroll
        for (int h = 0; h < 2; h++) {
            float x = p[mi][h];
            x += __shfl_xor_sync(0xffffffffu, x, 1);
            x += __shfl_xor_sync(0xffffffffu, x, 2);
            p[mi][h] = x;
        }
    __syncthreads();
    if (qid == 0) {
        #pragma unroll
        for (int mi = 0; mi < 2; mi++)
            #pragma unroll
            for (int h = 0; h < 2; h++)
                if (mi < MI)
                    s_half[wn*128 + wm*rowBand + mi*16 + gid + h*8] = p[mi][h];
    }
    __syncthreads();
    if (qid == 0 && wn == 0) {
        #pragma unroll
        for (int mi = 0; mi < 2; mi++)
            #pragma unroll
            for (int h = 0; h < 2; h++)
                if (mi < MI) {
                    const int r = wm*rowBand + mi*16 + gid + h*8;
                    g_att[row0 + r] = p[mi][h] + s_half[128 + r]
                                    + s_half[256 + r] + s_half[384 + r];
                }
    }

    // ---- fused per-batch softmax (last-arriver runs it) ----
    __threadfence();
    __syncthreads();
    if (tid == 0) {
        const int target = (b < 27) ? 16 : ((b == 27) ? 20 : 32);
        const int old = atomicAdd(&g_done[b], 1);
        s_last = (old == target - 1) ? 1 : 0;
    }
    __syncthreads();
    if (s_last) {
        __threadfence();
        const int len = lens[b];
        const float NEG_INF = __int_as_float(0xff800000);
        float v[4];
        float mx = NEG_INF;
        #pragma unroll
        for (int j = 0; j < 4; j++) {
            const int i = tid + j*512;
            float x = (i < len) ? g_att[b*Ss + i] : NEG_INF;
            v[j] = x;
            mx = fmaxf(mx, x);
        }
        #pragma unroll
        for (int m = 16; m >= 1; m >>= 1)
            mx = fmaxf(mx, __shfl_xor_sync(0xffffffffu, mx, m));
        if (lane == 0) s_red[wid] = mx;
        __syncthreads();
        if (tid == 0) {
            float m = s_red[0];
            #pragma unroll
            for (int i = 1; i < 16; i++) m = fmaxf(m, s_red[i]);
            s_red[16] = m;
        }
        __syncthreads();
        mx = s_red[16];

        float sum = 0.f;
        #pragma unroll
        for (int j = 0; j < 4; j++) {
            float e = __expf(v[j] - mx);
            v[j] = e;
            sum += e;
        }
        #pragma unroll
        for (int m = 16; m >= 1; m >>= 1)
            sum += __shfl_xor_sync(0xffffffffu, sum, m);
        __syncthreads();
        if (lane == 0) s_red[wid] = sum;
        __syncthreads();
        if (tid == 0) {
            float t = 0.f;
            #pragma unroll
            for (int i = 0; i < 16; i++) t += s_red[i];
            s_red[16] = t;
        }
        __syncthreads();
        const float inv = __fdividef(1.0f, s_red[16]);

        #pragma unroll
        for (int j = 0; j < 4; j++) {
            const int i = tid + j*512;
            const float w = v[j] * inv;
            out[b*Ss + i] = w;
            out[NROWS + b*Ss + i] = cov[b*Ss + i] + w;
        }
        if (tid == 0) g_done[b] = 0;   // reset for next graph replay
    }
}

// ---------------------------------------------------------------------------
extern "C" void kernel_launch(void* const* d_in, const int* in_sizes, int n_in,
                              void* d_out, int out_size) {
    const float* dec_input = (const float*)d_in[0];
    const float* enc       = (const float*)d_in[1];
    const int*   lens      = (const int*)  d_in[2];
    const float* cov       = (const float*)d_in[3];
    const float* W         = (const float*)d_in[4];
    const float* bias      = (const float*)d_in[5];
    const float* v_w       = (const float*)d_in[6];
    float* out = (float*)d_out;

    prep_kernel<<<528, 256>>>(dec_input, W);

    static int configured = 0;
    if (!configured) {
        cudaFuncSetAttribute(gemm_kernel,
                             cudaFuncAttributeMaxDynamicSharedMemorySize, SMEM_DYN);
        configured = 1;
    }
    gemm_kernel<<<NFULL + NHALF, 512, SMEM_DYN>>>(enc, cov, v_w, bias, lens, out);
}

// round 14
// speedup vs baseline: 1.0688x; 1.0688x over previous
#include <cuda_runtime.h>
#include <cuda_fp16.h>
#include <cstdint>

#define Bb 32
#define Ss 2048
#define Hh 512
#define Ee 512
#define NROWS (Bb*Ss)

#define NFULL 444                     // full M=128 tiles (= 3*148)
#define NHALF 136                     // half M=64 tiles at grid end (LPT)
#define ROWS_FULL (NFULL*128)         // 56832

// ---- device scratch ----
// Fragment-major B: [K(32)][J(64)][lane(32)] -> uint2 {b0,b1}
__device__ uint2  g_Wfrag[32*64*32];
__device__ float  g_dvpart[8*Bb*Hh];
__device__ float  g_wcpart[16*Hh];
__device__ float  g_att[NROWS];

// ---- GEMM geometry ----
#define AS_STRIDE 520
#define AS_BYTES (128*AS_STRIDE*2)    // 133120
#define OFF_DVEC AS_BYTES
#define OFF_WC   (OFF_DVEC + 2048)
#define OFF_VW   (OFF_WC + 2048)
#define OFF_COV  (OFF_VW + 2048)
#define OFF_HALF (OFF_COV + 512)
#define SMEM_DYN (OFF_HALF + 4*128*4)   // 141824

__device__ __forceinline__ uint32_t smem_u32(const void* p) {
    uint32_t a;
    asm("{ .reg .u64 t; cvta.to.shared.u64 t, %1; cvt.u32.u64 %0, t; }" : "=r"(a) : "l"(p));
    return a;
}

#define LDMX4(r0, r1, r2, r3, a) \
    asm volatile("ldmatrix.sync.aligned.m8n8.x4.shared.b16 {%0,%1,%2,%3}, [%4];" \
        : "=r"(r0), "=r"(r1), "=r"(r2), "=r"(r3) : "r"(a))

__device__ __forceinline__ void mma_f16(float* c, const uint32_t* a,
                                        uint32_t b0, uint32_t b1) {
    asm volatile(
        "mma.sync.aligned.m16n8k16.row.col.f32.f16.f16.f32 "
        "{%0,%1,%2,%3}, {%4,%5,%6,%7}, {%8,%9}, {%0,%1,%2,%3};"
        : "+f"(c[0]), "+f"(c[1]), "+f"(c[2]), "+f"(c[3])
        : "r"(a[0]), "r"(a[1]), "r"(a[2]), "r"(a[3]), "r"(b0), "r"(b1));
}

// ---------------------------------------------------------------------------
// prep (528 blocks x 256)
//  blk <256 : W_enc -> fragment-major fp16 g_Wfrag (32x32 tile per block)
//  blk <512 : dec_proj partials    blk <528 : wc partials
// ---------------------------------------------------------------------------
__global__ void prep_kernel(const float* __restrict__ dec_input,
                            const float* __restrict__ W) {
    const int blk = blockIdx.x, tid = threadIdx.x;
    if (blk < 256) {
        __shared__ float t[32][33];            // t[k_local][n_local]
        const int bc = blk & 15, br = blk >> 4;   // n-tile bc, k-tile br
        const int lx = tid & 31, ly = tid >> 5;
        #pragma unroll
        for (int i = 0; i < 4; i++)
            t[ly + 8*i][lx] = W[(size_t)(br*32 + ly + 8*i)*Hh + bc*32 + lx];
        __syncthreads();
        // 8 warps -> 8 (J,K) sub-blocks: Jl = w&3 (4 n8-groups), Kl = w>>2 (2 k16-groups)
        const int w = tid >> 5, l = tid & 31;
        const int Jl = w & 3, Kl = w >> 2;
        const int kb = Kl*16 + (l & 3)*2;      // local k base
        const int nl = Jl*8 + (l >> 2);        // local n
        uint16_t u0 = __half_as_ushort(__float2half_rn(t[kb + 0][nl]));
        uint16_t u1 = __half_as_ushort(__float2half_rn(t[kb + 1][nl]));
        uint16_t u2 = __half_as_ushort(__float2half_rn(t[kb + 8][nl]));
        uint16_t u3 = __half_as_ushort(__float2half_rn(t[kb + 9][nl]));
        uint2 val;
        val.x = (uint32_t)u0 | ((uint32_t)u1 << 16);
        val.y = (uint32_t)u2 | ((uint32_t)u3 << 16);
        const int J = bc*4 + Jl, K = br*2 + Kl;
        g_Wfrag[(K*64 + J)*32 + l] = val;
    } else if (blk < 512) {
        const int loc = blk - 256;
        const int b = loc >> 3, ec = loc & 7;
        __shared__ float sdec[64];
        if (tid < 64) sdec[tid] = dec_input[b*Ee + ec*64 + tid];
        __syncthreads();
        const float* Ws = W + (size_t)(Hh + ec*64) * Hh;
        const int h0 = tid, h1 = tid + 256;
        float a0 = 0.f, a1 = 0.f;
        #pragma unroll 8
        for (int e = 0; e < 64; e++) {
            const float d = sdec[e];
            a0 = fmaf(d, Ws[(size_t)e*Hh + h0], a0);
            a1 = fmaf(d, Ws[(size_t)e*Hh + h1], a1);
        }
        g_dvpart[(size_t)(ec*Bb + b)*Hh + h0] = a0;
        g_dvpart[(size_t)(ec*Bb + b)*Hh + h1] = a1;
    } else {
        const int p = blk - 512;
        const float* Wc = W + (size_t)(Hh + Ee + p*32) * Hh;
        const int h0 = tid, h1 = tid + 256;
        float a0 = 0.f, a1 = 0.f;
        #pragma unroll
        for (int r = 0; r < 32; r++) {
            a0 += Wc[(size_t)r*Hh + h0];
            a1 += Wc[(size_t)r*Hh + h1];
        }
        g_wcpart[p*Hh + h0] = a0;
        g_wcpart[p*Hh + h1] = a1;
    }
}

// ---------------------------------------------------------------------------
// GEMM: 580 CTAs, 512 threads (4M x 4N warps). B fragments via direct LDG.64
// from fragment-major g_Wfrag (L2-resident). NO smem B, NO cp.async, NO
// mainloop barriers — warps run free after the single A-load barrier.
// ---------------------------------------------------------------------------
__global__ __launch_bounds__(512, 1) void gemm_kernel(
    const float* __restrict__ enc,
    const float* __restrict__ cov,
    const float* __restrict__ v_w,
    const float* __restrict__ bias)
{
    extern __shared__ char sm[];
    float* s_dvec = (float*)(sm + OFF_DVEC);
    float* s_wc   = (float*)(sm + OFF_WC);
    float* s_vw   = (float*)(sm + OFF_VW);
    float* s_cov  = (float*)(sm + OFF_COV);
    float* s_half = (float*)(sm + OFF_HALF);   // [4][128]

    const uint32_t sb = smem_u32(sm);
    const int tid = threadIdx.x;
    const int wid = tid >> 5, lane = tid & 31;
    const int gid = lane >> 2, qid = lane & 3;
    const int wm = wid >> 2, wn = wid & 3;     // 4 x 4 warp grid

    const int isFull  = (blockIdx.x < NFULL);
    const int MI      = isFull ? 2 : 1;
    const int mrows   = isFull ? 128 : 64;
    const int rowBand = isFull ? 32 : 16;
    const int row0    = isFull ? blockIdx.x * 128
                               : ROWS_FULL + (blockIdx.x - NFULL) * 64;
    const int b = row0 >> 11;

    // epilogue constants
    for (int i = tid; i < Hh; i += 512) {
        float dv = bias[i];
        #pragma unroll
        for (int ec = 0; ec < 8; ec++) dv += g_dvpart[(size_t)(ec*Bb + b)*Hh + i];
        s_dvec[i] = dv;
        float w = 0.f;
        #pragma unroll
        for (int p = 0; p < 16; p++) w += g_wcpart[p*Hh + i];
        s_wc[i] = w;
        s_vw[i] = v_w[i];
    }
    if (tid < mrows) s_cov[tid] = cov[row0 + tid];

    // A tile: mrows x 512 fp32 -> fp16 smem (only smem tile in the kernel)
    {
        const float4* encv = (const float4*)(enc + (size_t)row0 * Hh);
        const int nIter = mrows >> 2;
        #pragma unroll 8
        for (int i = 0; i < nIter; i++) {
            int idx = tid + i*512;
            int r = idx >> 7, c4 = idx & 127;
            float4 v = encv[r*128 + c4];
            __half2 h0 = __float22half2_rn(make_float2(v.x, v.y));
            __half2 h1 = __float22half2_rn(make_float2(v.z, v.w));
            char* dst = sm + r*(AS_STRIDE*2) + c4*8;
            *(__half2*)dst = h0;
            *(__half2*)(dst + 4) = h1;
        }
    }
    __syncthreads();   // the ONLY pre-mainloop barrier

    const uint32_t baseA = sb
        + (uint32_t)(wm*rowBand + ((lane>>3)&1)*8 + (lane&7)) * (AS_STRIDE*2)
        + (uint32_t)((lane>>4)&1) * 16;

    float p[2][2] = {{0.f, 0.f}, {0.f, 0.f}};
    float acc[2][4][4];

    #pragma unroll 1
    for (int q = 0; q < 32; q++) {
        const int nc = q >> 3, kc = q & 7;
        if (kc == 0) {
            #pragma unroll
            for (int mi = 0; mi < 2; mi++)
                #pragma unroll
                for (int j = 0; j < 4; j++)
                    #pragma unroll
                    for (int c = 0; c < 4; c++) acc[mi][j][c] = 0.f;
        }

        // B fragments for this iteration: 16x LDG.64, fully coalesced per warp
        uint2 bf[4][4];
        const int Jb = nc*16 + wn*4;
        #pragma unroll
        for (int ks = 0; ks < 4; ks++) {
            const int K = kc*4 + ks;
            #pragma unroll
            for (int jn = 0; jn < 4; jn++)
                bf[ks][jn] = __ldg(&g_Wfrag[(K*64 + Jb + jn)*32 + lane]);
        }

        #pragma unroll
        for (int ks = 0; ks < 4; ks++) {
            uint32_t a[2][4];
            const uint32_t aAddr = baseA + (uint32_t)(kc*64 + ks*16)*2;
            LDMX4(a[0][0], a[0][1], a[0][2], a[0][3], aAddr);
            if (MI == 2)
                LDMX4(a[1][0], a[1][1], a[1][2], a[1][3], aAddr + 16*(AS_STRIDE*2));

            #pragma unroll
            for (int jn = 0; jn < 4; jn++) {
                mma_f16(acc[0][jn], a[0], bf[ks][jn].x, bf[ks][jn].y);
                if (MI == 2)
                    mma_f16(acc[1][jn], a[1], bf[ks][jn].x, bf[ks][jn].y);
            }
        }

        if (kc == 7) {
            #pragma unroll
            for (int mi = 0; mi < 2; mi++) {
                if (mi >= MI) break;
                const int r0 = wm*rowBand + mi*16 + gid;
                const float cv0 = s_cov[r0], cv1 = s_cov[r0 + 8];
                #pragma unroll
                for (int j = 0; j < 4; j++) {
                    const int n0 = nc*128 + wn*32 + j*8 + qid*2;
                    const float d0 = s_dvec[n0], d1 = s_dvec[n0+1];
                    const float w0 = s_wc[n0],   w1 = s_wc[n0+1];
                    const float v0 = s_vw[n0],   v1 = s_vw[n0+1];
                    float z, t;
                    z = acc[mi][j][0] + d0 + cv0*w0;
                    asm("tanh.approx.f32 %0, %1;" : "=f"(t) : "f"(z));  p[mi][0] = fmaf(v0, t, p[mi][0]);
                    z = acc[mi][j][1] + d1 + cv0*w1;
                    asm("tanh.approx.f32 %0, %1;" : "=f"(t) : "f"(z));  p[mi][0] = fmaf(v1, t, p[mi][0]);
                    z = acc[mi][j][2] + d0 + cv1*w0;
                    asm("tanh.approx.f32 %0, %1;" : "=f"(t) : "f"(z));  p[mi][1] = fmaf(v0, t, p[mi][1]);
                    z = acc[mi][j][3] + d1 + cv1*w1;
                    asm("tanh.approx.f32 %0, %1;" : "=f"(t) : "f"(z));  p[mi][1] = fmaf(v1, t, p[mi][1]);
                }
            }
        }
    }

    // reduce over qid lanes; combine the 4 wn bands via smem; store
    #pragma unroll
    for (int mi = 0; mi < 2; mi++)
        #pragma unroll
        for (int h = 0; h < 2; h++) {
            float x = p[mi][h];
            x += __shfl_xor_sync(0xffffffffu, x, 1);
            x += __shfl_xor_sync(0xffffffffu, x, 2);
            p[mi][h] = x;
        }
    __syncthreads();
    if (qid == 0) {
        #pragma unroll
        for (int mi = 0; mi < 2; mi++)
            #pragma unroll
            for (int h = 0; h < 2; h++)
                if (mi < MI)
                    s_half[wn*128 + wm*rowBand + mi*16 + gid + h*8] = p[mi][h];
    }
    __syncthreads();
    if (qid == 0 && wn == 0) {
        #pragma unroll
        for (int mi = 0; mi < 2; mi++)
            #pragma unroll
            for (int h = 0; h < 2; h++)
                if (mi < MI) {
                    const int r = wm*rowBand + mi*16 + gid + h*8;
                    g_att[row0 + r] = p[mi][h] + s_half[128 + r]
                                    + s_half[256 + r] + s_half[384 + r];
                }
    }
}

// ---------------------------------------------------------------------------
// softmax + coverage: separate kernel (round-11 proven)
// ---------------------------------------------------------------------------
__global__ __launch_bounds__(512) void softmax_kernel(
    const int* __restrict__ lens,
    const float* __restrict__ cov,
    float* __restrict__ out)
{
    __shared__ float red[17];
    const int b = blockIdx.x;
    const int tid = threadIdx.x;
    const int len = lens[b];
    const float NEG_INF = __int_as_float(0xff800000);

    float v[4];
    float mx = NEG_INF;
    #pragma unroll
    for (int j = 0; j < 4; j++) {
        const int i = tid + j*512;
        float x = (i < len) ? g_att[b*Ss + i] : NEG_INF;
        v[j] = x;
        mx = fmaxf(mx, x);
    }
    #pragma unroll
    for (int m = 16; m >= 1; m >>= 1)
        mx = fmaxf(mx, __shfl_xor_sync(0xffffffffu, mx, m));
    if ((tid & 31) == 0) red[tid >> 5] = mx;
    __syncthreads();
    if (tid == 0) {
        float m = red[0];
        #pragma unroll
        for (int i = 1; i < 16; i++) m = fmaxf(m, red[i]);
        red[16] = m;
    }
    __syncthreads();
    mx = red[16];

    float sum = 0.f;
    #pragma unroll
    for (int j = 0; j < 4; j++) {
        float e = __expf(v[j] - mx);
        v[j] = e;
        sum += e;
    }
    #pragma unroll
    for (int m = 16; m >= 1; m >>= 1)
        sum += __shfl_xor_sync(0xffffffffu, sum, m);
    __syncthreads();
    if ((tid & 31) == 0) red[tid >> 5] = sum;
    __syncthreads();
    if (tid == 0) {
        float t = 0.f;
        #pragma unroll
        for (int i = 0; i < 16; i++) t += red[i];
        red[16] = t;
    }
    __syncthreads();
    const float inv = __fdividef(1.0f, red[16]);

    #pragma unroll
    for (int j = 0; j < 4; j++) {
        const int i = tid + j*512;
        const float w = v[j] * inv;
        out[b*Ss + i] = w;
        out[NROWS + b*Ss + i] = cov[b*Ss + i] + w;
    }
}

// ---------------------------------------------------------------------------
extern "C" void kernel_launch(void* const* d_in, const int* in_sizes, int n_in,
                              void* d_out, int out_size) {
    const float* dec_input = (const float*)d_in[0];
    const float* enc       = (const float*)d_in[1];
    const int*   lens      = (const int*)  d_in[2];
    const float* cov       = (const float*)d_in[3];
    const float* W         = (const float*)d_in[4];
    const float* bias      = (const float*)d_in[5];
    const float* v_w       = (const float*)d_in[6];
    float* out = (float*)d_out;

    prep_kernel<<<528, 256>>>(dec_input, W);

    static int configured = 0;
    if (!configured) {
        cudaFuncSetAttribute(gemm_kernel,
                             cudaFuncAttributeMaxDynamicSharedMemorySize, SMEM_DYN);
        configured = 1;
    }
    gemm_kernel<<<NFULL + NHALF, 512, SMEM_DYN>>>(enc, cov, v_w, bias);

    softmax_kernel<<<Bb, 512>>>(lens, cov, out);
}

// round 15
// speedup vs baseline: 1.2162x; 1.1379x over previous
#include <cuda_runtime.h>
#include <cuda_fp16.h>
#include <cstdint>

#define Bb 32
#define Ss 2048
#define Hh 512
#define Ee 512
#define NROWS (Bb*Ss)

#define NFULL 444                     // full M=128 tiles (= 3*148)
#define NHALF 136                     // half M=64 tiles at grid end (LPT)
#define ROWS_FULL (NFULL*128)         // 56832

// ---- device scratch ----
// Fragment-major B, LDG.128: [K2(16)][J(64)][lane(32)] -> uint4
//   x,y = (b0,b1) of K = 2*K2 ;  z,w = (b0,b1) of K = 2*K2+1
__device__ uint4  g_Wfrag4[16*64*32];
__device__ float  g_dvpart[8*Bb*Hh];
__device__ float  g_wcpart[16*Hh];
__device__ float  g_att[NROWS];

// ---- GEMM geometry ----
#define AS_STRIDE 520
#define AS_BYTES (128*AS_STRIDE*2)    // 133120
#define OFF_DVEC AS_BYTES
#define OFF_WC   (OFF_DVEC + 2048)
#define OFF_VW   (OFF_WC + 2048)
#define OFF_COV  (OFF_VW + 2048)
#define OFF_HALF (OFF_COV + 512)
#define SMEM_DYN (OFF_HALF + 4*128*4)   // 141824

__device__ __forceinline__ uint32_t smem_u32(const void* p) {
    uint32_t a;
    asm("{ .reg .u64 t; cvta.to.shared.u64 t, %1; cvt.u32.u64 %0, t; }" : "=r"(a) : "l"(p));
    return a;
}

#define LDMX4(r0, r1, r2, r3, a) \
    asm volatile("ldmatrix.sync.aligned.m8n8.x4.shared.b16 {%0,%1,%2,%3}, [%4];" \
        : "=r"(r0), "=r"(r1), "=r"(r2), "=r"(r3) : "r"(a))

__device__ __forceinline__ void mma_f16(float* c, const uint32_t* a,
                                        uint32_t b0, uint32_t b1) {
    asm volatile(
        "mma.sync.aligned.m16n8k16.row.col.f32.f16.f16.f32 "
        "{%0,%1,%2,%3}, {%4,%5,%6,%7}, {%8,%9}, {%0,%1,%2,%3};"
        : "+f"(c[0]), "+f"(c[1]), "+f"(c[2]), "+f"(c[3])
        : "r"(a[0]), "r"(a[1]), "r"(a[2]), "r"(a[3]), "r"(b0), "r"(b1));
}

// ---------------------------------------------------------------------------
// prep (528 blocks x 256)
//  blk <256 : W_enc 32x32 tile -> uint4 fragment-major g_Wfrag4
//  blk <512 : dec_proj partials    blk <528 : wc partials
// ---------------------------------------------------------------------------
__global__ void prep_kernel(const float* __restrict__ dec_input,
                            const float* __restrict__ W) {
    const int blk = blockIdx.x, tid = threadIdx.x;
    if (blk < 256) {
        __shared__ float t[32][33];            // t[k_local][n_local]
        const int bc = blk & 15, br = blk >> 4;   // n-tile bc, k-tile br (32 k = one K2)
        const int lx = tid & 31, ly = tid >> 5;
        #pragma unroll
        for (int i = 0; i < 4; i++)
            t[ly + 8*i][lx] = W[(size_t)(br*32 + ly + 8*i)*Hh + bc*32 + lx];
        __syncthreads();
        // 4 warps -> 4 J-subgroups; each lane builds one uint4 (both K of this K2)
        const int w = tid >> 5, l = tid & 31;
        if (w < 4) {
            const int nl = w*8 + (l >> 2);          // local n
            const int kb = (l & 3)*2;               // local k base in K-even group
            #define PK(ka) ((uint32_t)__half_as_ushort(__float2half_rn(t[(ka)][nl])) | \
                            ((uint32_t)__half_as_ushort(__float2half_rn(t[(ka)+1][nl])) << 16))
            uint4 val;
            val.x = PK(kb);        // K even, b0  (k, k+1)
            val.y = PK(kb + 8);    // K even, b1  (k+8, k+9)
            val.z = PK(kb + 16);   // K odd,  b0
            val.w = PK(kb + 24);   // K odd,  b1
            #undef PK
            const int J = bc*4 + w, K2 = br;
            g_Wfrag4[(K2*64 + J)*32 + l] = val;
        }
    } else if (blk < 512) {
        const int loc = blk - 256;
        const int b = loc >> 3, ec = loc & 7;
        __shared__ float sdec[64];
        if (tid < 64) sdec[tid] = dec_input[b*Ee + ec*64 + tid];
        __syncthreads();
        const float* Ws = W + (size_t)(Hh + ec*64) * Hh;
        const int h0 = tid, h1 = tid + 256;
        float a0 = 0.f, a1 = 0.f;
        #pragma unroll 8
        for (int e = 0; e < 64; e++) {
            const float d = sdec[e];
            a0 = fmaf(d, Ws[(size_t)e*Hh + h0], a0);
            a1 = fmaf(d, Ws[(size_t)e*Hh + h1], a1);
        }
        g_dvpart[(size_t)(ec*Bb + b)*Hh + h0] = a0;
        g_dvpart[(size_t)(ec*Bb + b)*Hh + h1] = a1;
    } else {
        const int p = blk - 512;
        const float* Wc = W + (size_t)(Hh + Ee + p*32) * Hh;
        const int h0 = tid, h1 = tid + 256;
        float a0 = 0.f, a1 = 0.f;
        #pragma unroll
        for (int r = 0; r < 32; r++) {
            a0 += Wc[(size_t)r*Hh + h0];
            a1 += Wc[(size_t)r*Hh + h1];
        }
        g_wcpart[p*Hh + h0] = a0;
        g_wcpart[p*Hh + h1] = a1;
    }
}

// ---------------------------------------------------------------------------
// GEMM: 580 CTAs, 512 threads (4M x 4N warps). B fragments via LDG.128 from
// fragment-major g_Wfrag4 (L2-resident). No smem B, no mainloop barriers.
// ---------------------------------------------------------------------------
__global__ __launch_bounds__(512, 1) void gemm_kernel(
    const float* __restrict__ enc,
    const float* __restrict__ cov,
    const float* __restrict__ v_w,
    const float* __restrict__ bias)
{
    extern __shared__ char sm[];
    float* s_dvec = (float*)(sm + OFF_DVEC);
    float* s_wc   = (float*)(sm + OFF_WC);
    float* s_vw   = (float*)(sm + OFF_VW);
    float* s_cov  = (float*)(sm + OFF_COV);
    float* s_half = (float*)(sm + OFF_HALF);   // [4][128]

    const uint32_t sb = smem_u32(sm);
    const int tid = threadIdx.x;
    const int wid = tid >> 5, lane = tid & 31;
    const int gid = lane >> 2, qid = lane & 3;
    const int wm = wid >> 2, wn = wid & 3;     // 4 x 4 warp grid

    const int isFull  = (blockIdx.x < NFULL);
    const int MI      = isFull ? 2 : 1;
    const int mrows   = isFull ? 128 : 64;
    const int rowBand = isFull ? 32 : 16;
    const int row0    = isFull ? blockIdx.x * 128
                               : ROWS_FULL + (blockIdx.x - NFULL) * 64;
    const int b = row0 >> 11;

    // epilogue constants
    for (int i = tid; i < Hh; i += 512) {
        float dv = bias[i];
        #pragma unroll
        for (int ec = 0; ec < 8; ec++) dv += g_dvpart[(size_t)(ec*Bb + b)*Hh + i];
        s_dvec[i] = dv;
        float w = 0.f;
        #pragma unroll
        for (int p = 0; p < 16; p++) w += g_wcpart[p*Hh + i];
        s_wc[i] = w;
        s_vw[i] = v_w[i];
    }
    if (tid < mrows) s_cov[tid] = cov[row0 + tid];

    // A tile: mrows x 512 fp32 -> fp16 smem
    {
        const float4* encv = (const float4*)(enc + (size_t)row0 * Hh);
        const int nIter = mrows >> 2;
        #pragma unroll 8
        for (int i = 0; i < nIter; i++) {
            int idx = tid + i*512;
            int r = idx >> 7, c4 = idx & 127;
            float4 v = encv[r*128 + c4];
            __half2 h0 = __float22half2_rn(make_float2(v.x, v.y));
            __half2 h1 = __float22half2_rn(make_float2(v.z, v.w));
            char* dst = sm + r*(AS_STRIDE*2) + c4*8;
            *(__half2*)dst = h0;
            *(__half2*)(dst + 4) = h1;
        }
    }
    __syncthreads();   // the ONLY pre-mainloop barrier

    const uint32_t baseA = sb
        + (uint32_t)(wm*rowBand + ((lane>>3)&1)*8 + (lane&7)) * (AS_STRIDE*2)
        + (uint32_t)((lane>>4)&1) * 16;

    float p[2][2] = {{0.f, 0.f}, {0.f, 0.f}};
    float acc[2][4][4];

    #pragma unroll 1
    for (int q = 0; q < 32; q++) {
        const int nc = q >> 3, kc = q & 7;
        if (kc == 0) {
            #pragma unroll
            for (int mi = 0; mi < 2; mi++)
                #pragma unroll
                for (int j = 0; j < 4; j++)
                    #pragma unroll
                    for (int c = 0; c < 4; c++) acc[mi][j][c] = 0.f;
        }

        // B fragments: 8x LDG.128, fully coalesced per warp (512 B / load)
        uint4 bf[2][4];
        const int Jb = nc*16 + wn*4;
        #pragma unroll
        for (int ksp = 0; ksp < 2; ksp++) {
            const int K2 = kc*2 + ksp;
            #pragma unroll
            for (int jn = 0; jn < 4; jn++)
                bf[ksp][jn] = __ldg(&g_Wfrag4[(K2*64 + Jb + jn)*32 + lane]);
        }

        #pragma unroll
        for (int ksp = 0; ksp < 2; ksp++) {
            #pragma unroll
            for (int ko = 0; ko < 2; ko++) {       // K even / K odd within uint4
                const int ks = ksp*2 + ko;
                uint32_t a[2][4];
                const uint32_t aAddr = baseA + (uint32_t)(kc*64 + ks*16)*2;
                LDMX4(a[0][0], a[0][1], a[0][2], a[0][3], aAddr);
                if (MI == 2)
                    LDMX4(a[1][0], a[1][1], a[1][2], a[1][3], aAddr + 16*(AS_STRIDE*2));

                #pragma unroll
                for (int jn = 0; jn < 4; jn++) {
                    const uint32_t b0 = ko ? bf[ksp][jn].z : bf[ksp][jn].x;
                    const uint32_t b1 = ko ? bf[ksp][jn].w : bf[ksp][jn].y;
                    mma_f16(acc[0][jn], a[0], b0, b1);
                    if (MI == 2)
                        mma_f16(acc[1][jn], a[1], b0, b1);
                }
            }
        }

        if (kc == 7) {
            #pragma unroll
            for (int mi = 0; mi < 2; mi++) {
                if (mi >= MI) break;
                const int r0 = wm*rowBand + mi*16 + gid;
                const float cv0 = s_cov[r0], cv1 = s_cov[r0 + 8];
                #pragma unroll
                for (int j = 0; j < 4; j++) {
                    const int n0 = nc*128 + wn*32 + j*8 + qid*2;
                    const float d0 = s_dvec[n0], d1 = s_dvec[n0+1];
                    const float w0 = s_wc[n0],   w1 = s_wc[n0+1];
                    const float v0 = s_vw[n0],   v1 = s_vw[n0+1];
                    float z, t;
                    z = acc[mi][j][0] + d0 + cv0*w0;
                    asm("tanh.approx.f32 %0, %1;" : "=f"(t) : "f"(z));  p[mi][0] = fmaf(v0, t, p[mi][0]);
                    z = acc[mi][j][1] + d1 + cv0*w1;
                    asm("tanh.approx.f32 %0, %1;" : "=f"(t) : "f"(z));  p[mi][0] = fmaf(v1, t, p[mi][0]);
                    z = acc[mi][j][2] + d0 + cv1*w0;
                    asm("tanh.approx.f32 %0, %1;" : "=f"(t) : "f"(z));  p[mi][1] = fmaf(v0, t, p[mi][1]);
                    z = acc[mi][j][3] + d1 + cv1*w1;
                    asm("tanh.approx.f32 %0, %1;" : "=f"(t) : "f"(z));  p[mi][1] = fmaf(v1, t, p[mi][1]);
                }
            }
        }
    }

    // reduce over qid lanes; combine the 4 wn bands via smem; store
    #pragma unroll
    for (int mi = 0; mi < 2; mi++)
        #pragma unroll
        for (int h = 0; h < 2; h++) {
            float x = p[mi][h];
            x += __shfl_xor_sync(0xffffffffu, x, 1);
            x += __shfl_xor_sync(0xffffffffu, x, 2);
            p[mi][h] = x;
        }
    __syncthreads();
    if (qid == 0) {
        #pragma unroll
        for (int mi = 0; mi < 2; mi++)
            #pragma unroll
            for (int h = 0; h < 2; h++)
                if (mi < MI)
                    s_half[wn*128 + wm*rowBand + mi*16 + gid + h*8] = p[mi][h];
    }
    __syncthreads();
    if (qid == 0 && wn == 0) {
        #pragma unroll
        for (int mi = 0; mi < 2; mi++)
            #pragma unroll
            for (int h = 0; h < 2; h++)
                if (mi < MI) {
                    const int r = wm*rowBand + mi*16 + gid + h*8;
                    g_att[row0 + r] = p[mi][h] + s_half[128 + r]
                                    + s_half[256 + r] + s_half[384 + r];
                }
    }
}

// ---------------------------------------------------------------------------
// softmax + coverage: separate kernel (proven)
// ---------------------------------------------------------------------------
__global__ __launch_bounds__(512) void softmax_kernel(
    const int* __restrict__ lens,
    const float* __restrict__ cov,
    float* __restrict__ out)
{
    __shared__ float red[17];
    const int b = blockIdx.x;
    const int tid = threadIdx.x;
    const int len = lens[b];
    const float NEG_INF = __int_as_float(0xff800000);

    float v[4];
    float mx = NEG_INF;
    #pragma unroll
    for (int j = 0; j < 4; j++) {
        const int i = tid + j*512;
        float x = (i < len) ? g_att[b*Ss + i] : NEG_INF;
        v[j] = x;
        mx = fmaxf(mx, x);
    }
    #pragma unroll
    for (int m = 16; m >= 1; m >>= 1)
        mx = fmaxf(mx, __shfl_xor_sync(0xffffffffu, mx, m));
    if ((tid & 31) == 0) red[tid >> 5] = mx;
    __syncthreads();
    if (tid == 0) {
        float m = red[0];
        #pragma unroll
        for (int i = 1; i < 16; i++) m = fmaxf(m, red[i]);
        red[16] = m;
    }
    __syncthreads();
    mx = red[16];

    float sum = 0.f;
    #pragma unroll
    for (int j = 0; j < 4; j++) {
        float e = __expf(v[j] - mx);
        v[j] = e;
        sum += e;
    }
    #pragma unroll
    for (int m = 16; m >= 1; m >>= 1)
        sum += __shfl_xor_sync(0xffffffffu, sum, m);
    __syncthreads();
    if ((tid & 31) == 0) red[tid >> 5] = sum;
    __syncthreads();
    if (tid == 0) {
        float t = 0.f;
        #pragma unroll
        for (int i = 0; i < 16; i++) t += red[i];
        red[16] = t;
    }
    __syncthreads();
    const float inv = __fdividef(1.0f, red[16]);

    #pragma unroll
    for (int j = 0; j < 4; j++) {
        const int i = tid + j*512;
        const float w = v[j] * inv;
        out[b*Ss + i] = w;
        out[NROWS + b*Ss + i] = cov[b*Ss + i] + w;
    }
}

// ---------------------------------------------------------------------------
extern "C" void kernel_launch(void* const* d_in, const int* in_sizes, int n_in,
                              void* d_out, int out_size) {
    const float* dec_input = (const float*)d_in[0];
    const float* enc       = (const float*)d_in[1];
    const int*   lens      = (const int*)  d_in[2];
    const float* cov       = (const float*)d_in[3];
    const float* W         = (const float*)d_in[4];
    const float* bias      = (const float*)d_in[5];
    const float* v_w       = (const float*)d_in[6];
    float* out = (float*)d_out;

    prep_kernel<<<528, 256>>>(dec_input, W);

    static int configured = 0;
    if (!configured) {
        cudaFuncSetAttribute(gemm_kernel,
                             cudaFuncAttributeMaxDynamicSharedMemorySize, SMEM_DYN);
        configured = 1;
    }
    gemm_kernel<<<NFULL + NHALF, 512, SMEM_DYN>>>(enc, cov, v_w, bias);

    softmax_kernel<<<Bb, 512>>>(lens, cov, out);
}

// round 16
// speedup vs baseline: 1.2550x; 1.0319x over previous
#include <cuda_runtime.h>
#include <cuda_fp16.h>
#include <cstdint>

#define Bb 32
#define Ss 2048
#define Hh 512
#define Ee 512
#define NROWS (Bb*Ss)

#define NFULL 444                     // full M=128 tiles (= 3*148)
#define NHALF 136                     // half M=64 tiles at grid end (LPT)
#define ROWS_FULL (NFULL*128)         // 56832

// ---- device scratch ----
// Fragment-major B, LDG.128: [K2(16)][J(64)][lane(32)] -> uint4
//   x,y = (b0,b1) of K = 2*K2 ;  z,w = (b0,b1) of K = 2*K2+1
__device__ uint4  g_Wfrag4[16*64*32];
__device__ float  g_dvpart[8*Bb*Hh];
__device__ float  g_wcpart[16*Hh];
__device__ float  g_att[NROWS];

// ---- GEMM geometry ----
#define AS_STRIDE 520
#define AS_BYTES (128*AS_STRIDE*2)    // 133120
#define OFF_DVEC AS_BYTES
#define OFF_WC   (OFF_DVEC + 2048)
#define OFF_VW   (OFF_WC + 2048)
#define OFF_COV  (OFF_VW + 2048)
#define OFF_HALF (OFF_COV + 512)
#define SMEM_DYN (OFF_HALF + 4*128*4)   // 141824

__device__ __forceinline__ uint32_t smem_u32(const void* p) {
    uint32_t a;
    asm("{ .reg .u64 t; cvta.to.shared.u64 t, %1; cvt.u32.u64 %0, t; }" : "=r"(a) : "l"(p));
    return a;
}

#define LDMX4(r0, r1, r2, r3, a) \
    asm volatile("ldmatrix.sync.aligned.m8n8.x4.shared.b16 {%0,%1,%2,%3}, [%4];" \
        : "=r"(r0), "=r"(r1), "=r"(r2), "=r"(r3) : "r"(a))

__device__ __forceinline__ void mma_f16(float* c, const uint32_t* a,
                                        uint32_t b0, uint32_t b1) {
    asm volatile(
        "mma.sync.aligned.m16n8k16.row.col.f32.f16.f16.f32 "
        "{%0,%1,%2,%3}, {%4,%5,%6,%7}, {%8,%9}, {%0,%1,%2,%3};"
        : "+f"(c[0]), "+f"(c[1]), "+f"(c[2]), "+f"(c[3])
        : "r"(a[0]), "r"(a[1]), "r"(a[2]), "r"(a[3]), "r"(b0), "r"(b1));
}

// ---------------------------------------------------------------------------
// prep (528 blocks x 256): unchanged from round 15
// ---------------------------------------------------------------------------
__global__ void prep_kernel(const float* __restrict__ dec_input,
                            const float* __restrict__ W) {
    const int blk = blockIdx.x, tid = threadIdx.x;
    if (blk < 256) {
        __shared__ float t[32][33];            // t[k_local][n_local]
        const int bc = blk & 15, br = blk >> 4;
        const int lx = tid & 31, ly = tid >> 5;
        #pragma unroll
        for (int i = 0; i < 4; i++)
            t[ly + 8*i][lx] = W[(size_t)(br*32 + ly + 8*i)*Hh + bc*32 + lx];
        __syncthreads();
        const int w = tid >> 5, l = tid & 31;
        if (w < 4) {
            const int nl = w*8 + (l >> 2);
            const int kb = (l & 3)*2;
            #define PK(ka) ((uint32_t)__half_as_ushort(__float2half_rn(t[(ka)][nl])) | \
                            ((uint32_t)__half_as_ushort(__float2half_rn(t[(ka)+1][nl])) << 16))
            uint4 val;
            val.x = PK(kb);
            val.y = PK(kb + 8);
            val.z = PK(kb + 16);
            val.w = PK(kb + 24);
            #undef PK
            const int J = bc*4 + w, K2 = br;
            g_Wfrag4[(K2*64 + J)*32 + l] = val;
        }
    } else if (blk < 512) {
        const int loc = blk - 256;
        const int b = loc >> 3, ec = loc & 7;
        __shared__ float sdec[64];
        if (tid < 64) sdec[tid] = dec_input[b*Ee + ec*64 + tid];
        __syncthreads();
        const float* Ws = W + (size_t)(Hh + ec*64) * Hh;
        const int h0 = tid, h1 = tid + 256;
        float a0 = 0.f, a1 = 0.f;
        #pragma unroll 8
        for (int e = 0; e < 64; e++) {
            const float d = sdec[e];
            a0 = fmaf(d, Ws[(size_t)e*Hh + h0], a0);
            a1 = fmaf(d, Ws[(size_t)e*Hh + h1], a1);
        }
        g_dvpart[(size_t)(ec*Bb + b)*Hh + h0] = a0;
        g_dvpart[(size_t)(ec*Bb + b)*Hh + h1] = a1;
    } else {
        const int p = blk - 512;
        const float* Wc = W + (size_t)(Hh + Ee + p*32) * Hh;
        const int h0 = tid, h1 = tid + 256;
        float a0 = 0.f, a1 = 0.f;
        #pragma unroll
        for (int r = 0; r < 32; r++) {
            a0 += Wc[(size_t)r*Hh + h0];
            a1 += Wc[(size_t)r*Hh + h1];
        }
        g_wcpart[p*Hh + h0] = a0;
        g_wcpart[p*Hh + h1] = a1;
    }
}

// ---------------------------------------------------------------------------
// GEMM: 580 CTAs, 512 threads (4M x 4N warps). B fragments via LDG.128 with
// REGISTER DOUBLE-BUFFERING (prefetch next ksp step). No smem B, no barriers.
// ---------------------------------------------------------------------------
__global__ __launch_bounds__(512, 1) void gemm_kernel(
    const float* __restrict__ enc,
    const float* __restrict__ cov,
    const float* __restrict__ v_w,
    const float* __restrict__ bias)
{
    extern __shared__ char sm[];
    float* s_dvec = (float*)(sm + OFF_DVEC);
    float* s_wc   = (float*)(sm + OFF_WC);
    float* s_vw   = (float*)(sm + OFF_VW);
    float* s_cov  = (float*)(sm + OFF_COV);
    float* s_half = (float*)(sm + OFF_HALF);   // [4][128]

    const uint32_t sb = smem_u32(sm);
    const int tid = threadIdx.x;
    const int wid = tid >> 5, lane = tid & 31;
    const int gid = lane >> 2, qid = lane & 3;
    const int wm = wid >> 2, wn = wid & 3;     // 4 x 4 warp grid

    const int isFull  = (blockIdx.x < NFULL);
    const int MI      = isFull ? 2 : 1;
    const int mrows   = isFull ? 128 : 64;
    const int rowBand = isFull ? 32 : 16;
    const int row0    = isFull ? blockIdx.x * 128
                               : ROWS_FULL + (blockIdx.x - NFULL) * 64;
    const int b = row0 >> 11;

    // epilogue constants
    for (int i = tid; i < Hh; i += 512) {
        float dv = bias[i];
        #pragma unroll
        for (int ec = 0; ec < 8; ec++) dv += g_dvpart[(size_t)(ec*Bb + b)*Hh + i];
        s_dvec[i] = dv;
        float w = 0.f;
        #pragma unroll
        for (int p = 0; p < 16; p++) w += g_wcpart[p*Hh + i];
        s_wc[i] = w;
        s_vw[i] = v_w[i];
    }
    if (tid < mrows) s_cov[tid] = cov[row0 + tid];

    // A tile: mrows x 512 fp32 -> fp16 smem
    {
        const float4* encv = (const float4*)(enc + (size_t)row0 * Hh);
        const int nIter = mrows >> 2;
        #pragma unroll 8
        for (int i = 0; i < nIter; i++) {
            int idx = tid + i*512;
            int r = idx >> 7, c4 = idx & 127;
            float4 v = encv[r*128 + c4];
            __half2 h0 = __float22half2_rn(make_float2(v.x, v.y));
            __half2 h1 = __float22half2_rn(make_float2(v.z, v.w));
            char* dst = sm + r*(AS_STRIDE*2) + c4*8;
            *(__half2*)dst = h0;
            *(__half2*)(dst + 4) = h1;
        }
    }
    __syncthreads();   // the ONLY pre-mainloop barrier

    const uint32_t baseA = sb
        + (uint32_t)(wm*rowBand + ((lane>>3)&1)*8 + (lane&7)) * (AS_STRIDE*2)
        + (uint32_t)((lane>>4)&1) * 16;

    float p[2][2] = {{0.f, 0.f}, {0.f, 0.f}};
    float acc[2][4][4];

    // B fragment double buffer: slot = ksp (cur == ksp since steps alternate)
    uint4 bf[2][4];
    {
        const int Jb0 = wn*4;   // q=0: nc=0, K2=0
        #pragma unroll
        for (int jn = 0; jn < 4; jn++)
            bf[0][jn] = __ldg(&g_Wfrag4[(Jb0 + jn)*32 + lane]);
    }

    #pragma unroll 1
    for (int q = 0; q < 32; q++) {
        const int nc = q >> 3, kc = q & 7;
        if (kc == 0) {
            #pragma unroll
            for (int mi = 0; mi < 2; mi++)
                #pragma unroll
                for (int j = 0; j < 4; j++)
                    #pragma unroll
                    for (int c = 0; c < 4; c++) acc[mi][j][c] = 0.f;
        }

        #pragma unroll
        for (int ksp = 0; ksp < 2; ksp++) {
            // prefetch next step (q,ksp+1) or (q+1,0) into the alternate slot
            const int step = q*2 + ksp + 1;
            if (step < 64) {
                const int nq = step >> 1, nksp = step & 1;
                const int K2n = (nq & 7)*2 + nksp;
                const int Jbn = (nq >> 3)*16 + wn*4;
                #pragma unroll
                for (int jn = 0; jn < 4; jn++)
                    bf[ksp ^ 1][jn] = __ldg(&g_Wfrag4[(K2n*64 + Jbn + jn)*32 + lane]);
            }

            #pragma unroll
            for (int ko = 0; ko < 2; ko++) {       // K even / K odd within uint4
                const int ks = ksp*2 + ko;
                uint32_t a[2][4];
                const uint32_t aAddr = baseA + (uint32_t)(kc*64 + ks*16)*2;
                LDMX4(a[0][0], a[0][1], a[0][2], a[0][3], aAddr);
                if (MI == 2)
                    LDMX4(a[1][0], a[1][1], a[1][2], a[1][3], aAddr + 16*(AS_STRIDE*2));

                #pragma unroll
                for (int jn = 0; jn < 4; jn++) {
                    const uint32_t b0 = ko ? bf[ksp][jn].z : bf[ksp][jn].x;
                    const uint32_t b1 = ko ? bf[ksp][jn].w : bf[ksp][jn].y;
                    mma_f16(acc[0][jn], a[0], b0, b1);
                    if (MI == 2)
                        mma_f16(acc[1][jn], a[1], b0, b1);
                }
            }
        }

        if (kc == 7) {
            #pragma unroll
            for (int mi = 0; mi < 2; mi++) {
                if (mi >= MI) break;
                const int r0 = wm*rowBand + mi*16 + gid;
                const float cv0 = s_cov[r0], cv1 = s_cov[r0 + 8];
                #pragma unroll
                for (int j = 0; j < 4; j++) {
                    const int n0 = nc*128 + wn*32 + j*8 + qid*2;
                    const float d0 = s_dvec[n0], d1 = s_dvec[n0+1];
                    const float w0 = s_wc[n0],   w1 = s_wc[n0+1];
                    const float v0 = s_vw[n0],   v1 = s_vw[n0+1];
                    float z, t;
                    z = acc[mi][j][0] + d0 + cv0*w0;
                    asm("tanh.approx.f32 %0, %1;" : "=f"(t) : "f"(z));  p[mi][0] = fmaf(v0, t, p[mi][0]);
                    z = acc[mi][j][1] + d1 + cv0*w1;
                    asm("tanh.approx.f32 %0, %1;" : "=f"(t) : "f"(z));  p[mi][0] = fmaf(v1, t, p[mi][0]);
                    z = acc[mi][j][2] + d0 + cv1*w0;
                    asm("tanh.approx.f32 %0, %1;" : "=f"(t) : "f"(z));  p[mi][1] = fmaf(v0, t, p[mi][1]);
                    z = acc[mi][j][3] + d1 + cv1*w1;
                    asm("tanh.approx.f32 %0, %1;" : "=f"(t) : "f"(z));  p[mi][1] = fmaf(v1, t, p[mi][1]);
                }
            }
        }
    }

    // reduce over qid lanes; combine the 4 wn bands via smem; store
    #pragma unroll
    for (int mi = 0; mi < 2; mi++)
        #pragma unroll
        for (int h = 0; h < 2; h++) {
            float x = p[mi][h];
            x += __shfl_xor_sync(0xffffffffu, x, 1);
            x += __shfl_xor_sync(0xffffffffu, x, 2);
            p[mi][h] = x;
        }
    __syncthreads();
    if (qid == 0) {
        #pragma unroll
        for (int mi = 0; mi < 2; mi++)
            #pragma unroll
            for (int h = 0; h < 2; h++)
                if (mi < MI)
                    s_half[wn*128 + wm*rowBand + mi*16 + gid + h*8] = p[mi][h];
    }
    __syncthreads();
    if (qid == 0 && wn == 0) {
        #pragma unroll
        for (int mi = 0; mi < 2; mi++)
            #pragma unroll
            for (int h = 0; h < 2; h++)
                if (mi < MI) {
                    const int r = wm*rowBand + mi*16 + gid + h*8;
                    g_att[row0 + r] = p[mi][h] + s_half[128 + r]
                                    + s_half[256 + r] + s_half[384 + r];
                }
    }
}

// ---------------------------------------------------------------------------
// softmax + coverage: separate kernel (proven)
// ---------------------------------------------------------------------------
__global__ __launch_bounds__(512) void softmax_kernel(
    const int* __restrict__ lens,
    const float* __restrict__ cov,
    float* __restrict__ out)
{
    __shared__ float red[17];
    const int b = blockIdx.x;
    const int tid = threadIdx.x;
    const int len = lens[b];
    const float NEG_INF = __int_as_float(0xff800000);

    float v[4];
    float mx = NEG_INF;
    #pragma unroll
    for (int j = 0; j < 4; j++) {
        const int i = tid + j*512;
        float x = (i < len) ? g_att[b*Ss + i] : NEG_INF;
        v[j] = x;
        mx = fmaxf(mx, x);
    }
    #pragma unroll
    for (int m = 16; m >= 1; m >>= 1)
        mx = fmaxf(mx, __shfl_xor_sync(0xffffffffu, mx, m));
    if ((tid & 31) == 0) red[tid >> 5] = mx;
    __syncthreads();
    if (tid == 0) {
        float m = red[0];
        #pragma unroll
        for (int i = 1; i < 16; i++) m = fmaxf(m, red[i]);
        red[16] = m;
    }
    __syncthreads();
    mx = red[16];

    float sum = 0.f;
    #pragma unroll
    for (int j = 0; j < 4; j++) {
        float e = __expf(v[j] - mx);
        v[j] = e;
        sum += e;
    }
    #pragma unroll
    for (int m = 16; m >= 1; m >>= 1)
        sum += __shfl_xor_sync(0xffffffffu, sum, m);
    __syncthreads();
    if ((tid & 31) == 0) red[tid >> 5] = sum;
    __syncthreads();
    if (tid == 0) {
        float t = 0.f;
        #pragma unroll
        for (int i = 0; i < 16; i++) t += red[i];
        red[16] = t;
    }
    __syncthreads();
    const float inv = __fdividef(1.0f, red[16]);

    #pragma unroll
    for (int j = 0; j < 4; j++) {
        const int i = tid + j*512;
        const float w = v[j] * inv;
        out[b*Ss + i] = w;
        out[NROWS + b*Ss + i] = cov[b*Ss + i] + w;
    }
}

// ---------------------------------------------------------------------------
extern "C" void kernel_launch(void* const* d_in, const int* in_sizes, int n_in,
                              void* d_out, int out_size) {
    const float* dec_input = (const float*)d_in[0];
    const float* enc       = (const float*)d_in[1];
    const int*   lens      = (const int*)  d_in[2];
    const float* cov       = (const float*)d_in[3];
    const float* W         = (const float*)d_in[4];
    const float* bias      = (const float*)d_in[5];
    const float* v_w       = (const float*)d_in[6];
    float* out = (float*)d_out;

    prep_kernel<<<528, 256>>>(dec_input, W);

    static int configured = 0;
    if (!configured) {
        cudaFuncSetAttribute(gemm_kernel,
                             cudaFuncAttributeMaxDynamicSharedMemorySize, SMEM_DYN);
        configured = 1;
    }
    gemm_kernel<<<NFULL + NHALF, 512, SMEM_DYN>>>(enc, cov, v_w, bias);

    softmax_kernel<<<Bb, 512>>>(lens, cov, out);
}

// round 17
// speedup vs baseline: 1.2578x; 1.0022x over previous
#include <cuda_runtime.h>
#include <cuda_fp16.h>
#include <cstdint>

#define Bb 32
#define Ss 2048
#define Hh 512
#define Ee 512
#define NROWS (Bb*Ss)

#define NFULL 444                     // full M=128 tiles (= 3*148)
#define NHALF 136                     // half M=64 tiles at grid end (LPT)
#define ROWS_FULL (NFULL*128)         // 56832

// ---- device scratch ----
// Fragment-major B, LDG.128: [K2(16)][J(64)][lane(32)] -> uint4
__device__ uint4  g_Wfrag4[16*64*32];
__device__ float  g_dvpart[8*Bb*Hh];
__device__ float  g_wcpart[16*Hh];
__device__ float  g_att[NROWS];

// ---- GEMM geometry ----
#define AS_STRIDE 520
#define AS_BYTES (128*AS_STRIDE*2)    // 133120
#define OFF_DVEC AS_BYTES
#define OFF_WC   (OFF_DVEC + 2048)
#define OFF_VW   (OFF_WC + 2048)
#define OFF_COV  (OFF_VW + 2048)
#define OFF_HALF (OFF_COV + 512)
#define SMEM_DYN (OFF_HALF + 4*128*4)   // 141824

__device__ __forceinline__ uint32_t smem_u32(const void* p) {
    uint32_t a;
    asm("{ .reg .u64 t; cvta.to.shared.u64 t, %1; cvt.u32.u64 %0, t; }" : "=r"(a) : "l"(p));
    return a;
}

#define LDMX4(r0, r1, r2, r3, a) \
    asm volatile("ldmatrix.sync.aligned.m8n8.x4.shared.b16 {%0,%1,%2,%3}, [%4];" \
        : "=r"(r0), "=r"(r1), "=r"(r2), "=r"(r3) : "r"(a))

__device__ __forceinline__ void mma_f16(float* c, const uint32_t* a,
                                        uint32_t b0, uint32_t b1) {
    asm volatile(
        "mma.sync.aligned.m16n8k16.row.col.f32.f16.f16.f32 "
        "{%0,%1,%2,%3}, {%4,%5,%6,%7}, {%8,%9}, {%0,%1,%2,%3};"
        : "+f"(c[0]), "+f"(c[1]), "+f"(c[2]), "+f"(c[3])
        : "r"(a[0]), "r"(a[1]), "r"(a[2]), "r"(a[3]), "r"(b0), "r"(b1));
}

// ---------------------------------------------------------------------------
// prep (528 blocks x 256): triggers PDL early; higher-MLP load loops
// ---------------------------------------------------------------------------
__global__ void prep_kernel(const float* __restrict__ dec_input,
                            const float* __restrict__ W) {
    cudaTriggerProgrammaticLaunchCompletion();   // let gemm prologue start now
    const int blk = blockIdx.x, tid = threadIdx.x;
    if (blk < 256) {
        __shared__ float t[32][33];            // t[k_local][n_local]
        const int bc = blk & 15, br = blk >> 4;
        const int lx = tid & 31, ly = tid >> 5;
        #pragma unroll
        for (int i = 0; i < 4; i++)
            t[ly + 8*i][lx] = W[(size_t)(br*32 + ly + 8*i)*Hh + bc*32 + lx];
        __syncthreads();
        const int w = tid >> 5, l = tid & 31;
        if (w < 4) {
            const int nl = w*8 + (l >> 2);
            const int kb = (l & 3)*2;
            #define PK(ka) ((uint32_t)__half_as_ushort(__float2half_rn(t[(ka)][nl])) | \
                            ((uint32_t)__half_as_ushort(__float2half_rn(t[(ka)+1][nl])) << 16))
            uint4 val;
            val.x = PK(kb);
            val.y = PK(kb + 8);
            val.z = PK(kb + 16);
            val.w = PK(kb + 24);
            #undef PK
            const int J = bc*4 + w, K2 = br;
            g_Wfrag4[(K2*64 + J)*32 + l] = val;
        }
    } else if (blk < 512) {
        const int loc = blk - 256;
        const int b = loc >> 3, ec = loc & 7;
        __shared__ float sdec[64];
        if (tid < 64) sdec[tid] = dec_input[b*Ee + ec*64 + tid];
        __syncthreads();
        const float* Ws = W + (size_t)(Hh + ec*64) * Hh;
        const int h0 = tid, h1 = tid + 256;
        float a0 = 0.f, a1 = 0.f, c0 = 0.f, c1 = 0.f;
        #pragma unroll 16
        for (int e = 0; e < 64; e += 2) {
            const float d0 = sdec[e], d1 = sdec[e + 1];
            a0 = fmaf(d0, Ws[(size_t)e*Hh + h0], a0);
            a1 = fmaf(d0, Ws[(size_t)e*Hh + h1], a1);
            c0 = fmaf(d1, Ws[(size_t)(e+1)*Hh + h0], c0);
            c1 = fmaf(d1, Ws[(size_t)(e+1)*Hh + h1], c1);
        }
        g_dvpart[(size_t)(ec*Bb + b)*Hh + h0] = a0 + c0;
        g_dvpart[(size_t)(ec*Bb + b)*Hh + h1] = a1 + c1;
    } else {
        const int p = blk - 512;
        const float* Wc = W + (size_t)(Hh + Ee + p*32) * Hh;
        const int h0 = tid, h1 = tid + 256;
        float a0 = 0.f, a1 = 0.f, c0 = 0.f, c1 = 0.f;
        #pragma unroll
        for (int r = 0; r < 32; r += 2) {
            a0 += Wc[(size_t)r*Hh + h0];
            a1 += Wc[(size_t)r*Hh + h1];
            c0 += Wc[(size_t)(r+1)*Hh + h0];
            c1 += Wc[(size_t)(r+1)*Hh + h1];
        }
        g_wcpart[p*Hh + h0] = a0 + c0;
        g_wcpart[p*Hh + h1] = a1 + c1;
    }
}

// ---------------------------------------------------------------------------
// GEMM: 580 CTAs, 512 threads (4M x 4N warps). PDL: A-tile prologue overlaps
// prep; griddepsync before any prep-produced data. B via LDG.128 double-buffer.
// ---------------------------------------------------------------------------
__global__ __launch_bounds__(512, 1) void gemm_kernel(
    const float* __restrict__ enc,
    const float* __restrict__ cov,
    const float* __restrict__ v_w,
    const float* __restrict__ bias)
{
    extern __shared__ char sm[];
    float* s_dvec = (float*)(sm + OFF_DVEC);
    float* s_wc   = (float*)(sm + OFF_WC);
    float* s_vw   = (float*)(sm + OFF_VW);
    float* s_cov  = (float*)(sm + OFF_COV);
    float* s_half = (float*)(sm + OFF_HALF);   // [4][128]

    const uint32_t sb = smem_u32(sm);
    const int tid = threadIdx.x;
    const int wid = tid >> 5, lane = tid & 31;
    const int gid = lane >> 2, qid = lane & 3;
    const int wm = wid >> 2, wn = wid & 3;     // 4 x 4 warp grid

    const int isFull  = (blockIdx.x < NFULL);
    const int MI      = isFull ? 2 : 1;
    const int mrows   = isFull ? 128 : 64;
    const int rowBand = isFull ? 32 : 16;
    const int row0    = isFull ? blockIdx.x * 128
                               : ROWS_FULL + (blockIdx.x - NFULL) * 64;
    const int b = row0 >> 11;

    // ---- PDL prologue: everything here is independent of prep ----
    // A tile: mrows x 512 fp32 -> fp16 smem
    {
        const float4* encv = (const float4*)(enc + (size_t)row0 * Hh);
        const int nIter = mrows >> 2;
        #pragma unroll 8
        for (int i = 0; i < nIter; i++) {
            int idx = tid + i*512;
            int r = idx >> 7, c4 = idx & 127;
            float4 v = encv[r*128 + c4];
            __half2 h0 = __float22half2_rn(make_float2(v.x, v.y));
            __half2 h1 = __float22half2_rn(make_float2(v.z, v.w));
            char* dst = sm + r*(AS_STRIDE*2) + c4*8;
            *(__half2*)dst = h0;
            *(__half2*)(dst + 4) = h1;
        }
    }
    if (tid < mrows) s_cov[tid] = cov[row0 + tid];
    for (int i = tid; i < Hh; i += 512) s_vw[i] = v_w[i];

    // ---- wait for prep's writes to be visible ----
    cudaGridDependencySynchronize();

    // epilogue constants (prep-produced)
    for (int i = tid; i < Hh; i += 512) {
        float dv = bias[i];
        #pragma unroll
        for (int ec = 0; ec < 8; ec++) dv += g_dvpart[(size_t)(ec*Bb + b)*Hh + i];
        s_dvec[i] = dv;
        float w = 0.f;
        #pragma unroll
        for (int p = 0; p < 16; p++) w += g_wcpart[p*Hh + i];
        s_wc[i] = w;
    }

    // B fragment double buffer: initial load (prep-produced)
    uint4 bf[2][4];
    {
        const int Jb0 = wn*4;   // q=0: nc=0, K2=0
        #pragma unroll
        for (int jn = 0; jn < 4; jn++)
            bf[0][jn] = __ldg(&g_Wfrag4[(Jb0 + jn)*32 + lane]);
    }
    __syncthreads();   // the ONLY pre-mainloop barrier

    const uint32_t baseA = sb
        + (uint32_t)(wm*rowBand + ((lane>>3)&1)*8 + (lane&7)) * (AS_STRIDE*2)
        + (uint32_t)((lane>>4)&1) * 16;

    float p[2][2] = {{0.f, 0.f}, {0.f, 0.f}};
    float acc[2][4][4];

    #pragma unroll 1
    for (int q = 0; q < 32; q++) {
        const int nc = q >> 3, kc = q & 7;
        if (kc == 0) {
            #pragma unroll
            for (int mi = 0; mi < 2; mi++)
                #pragma unroll
                for (int j = 0; j < 4; j++)
                    #pragma unroll
                    for (int c = 0; c < 4; c++) acc[mi][j][c] = 0.f;
        }

        #pragma unroll
        for (int ksp = 0; ksp < 2; ksp++) {
            // prefetch next step into the alternate slot
            const int step = q*2 + ksp + 1;
            if (step < 64) {
                const int nq = step >> 1, nksp = step & 1;
                const int K2n = (nq & 7)*2 + nksp;
                const int Jbn = (nq >> 3)*16 + wn*4;
                #pragma unroll
                for (int jn = 0; jn < 4; jn++)
                    bf[ksp ^ 1][jn] = __ldg(&g_Wfrag4[(K2n*64 + Jbn + jn)*32 + lane]);
            }

            #pragma unroll
            for (int ko = 0; ko < 2; ko++) {
                const int ks = ksp*2 + ko;
                uint32_t a[2][4];
                const uint32_t aAddr = baseA + (uint32_t)(kc*64 + ks*16)*2;
                LDMX4(a[0][0], a[0][1], a[0][2], a[0][3], aAddr);
                if (MI == 2)
                    LDMX4(a[1][0], a[1][1], a[1][2], a[1][3], aAddr + 16*(AS_STRIDE*2));

                #pragma unroll
                for (int jn = 0; jn < 4; jn++) {
                    const uint32_t b0 = ko ? bf[ksp][jn].z : bf[ksp][jn].x;
                    const uint32_t b1 = ko ? bf[ksp][jn].w : bf[ksp][jn].y;
                    mma_f16(acc[0][jn], a[0], b0, b1);
                    if (MI == 2)
                        mma_f16(acc[1][jn], a[1], b0, b1);
                }
            }
        }

        if (kc == 7) {
            #pragma unroll
            for (int mi = 0; mi < 2; mi++) {
                if (mi >= MI) break;
                const int r0 = wm*rowBand + mi*16 + gid;
                const float cv0 = s_cov[r0], cv1 = s_cov[r0 + 8];
                #pragma unroll
                for (int j = 0; j < 4; j++) {
                    const int n0 = nc*128 + wn*32 + j*8 + qid*2;
                    const float d0 = s_dvec[n0], d1 = s_dvec[n0+1];
                    const float w0 = s_wc[n0],   w1 = s_wc[n0+1];
                    const float v0 = s_vw[n0],   v1 = s_vw[n0+1];
                    float z, t;
                    z = acc[mi][j][0] + d0 + cv0*w0;
                    asm("tanh.approx.f32 %0, %1;" : "=f"(t) : "f"(z));  p[mi][0] = fmaf(v0, t, p[mi][0]);
                    z = acc[mi][j][1] + d1 + cv0*w1;
                    asm("tanh.approx.f32 %0, %1;" : "=f"(t) : "f"(z));  p[mi][0] = fmaf(v1, t, p[mi][0]);
                    z = acc[mi][j][2] + d0 + cv1*w0;
                    asm("tanh.approx.f32 %0, %1;" : "=f"(t) : "f"(z));  p[mi][1] = fmaf(v0, t, p[mi][1]);
                    z = acc[mi][j][3] + d1 + cv1*w1;
                    asm("tanh.approx.f32 %0, %1;" : "=f"(t) : "f"(z));  p[mi][1] = fmaf(v1, t, p[mi][1]);
                }
            }
        }
    }

    // reduce over qid lanes; combine the 4 wn bands via smem; store
    #pragma unroll
    for (int mi = 0; mi < 2; mi++)
        #pragma unroll
        for (int h = 0; h < 2; h++) {
            float x = p[mi][h];
            x += __shfl_xor_sync(0xffffffffu, x, 1);
            x += __shfl_xor_sync(0xffffffffu, x, 2);
            p[mi][h] = x;
        }
    __syncthreads();
    if (qid == 0) {
        #pragma unroll
        for (int mi = 0; mi < 2; mi++)
            #pragma unroll
            for (int h = 0; h < 2; h++)
                if (mi < MI)
                    s_half[wn*128 + wm*rowBand + mi*16 + gid + h*8] = p[mi][h];
    }
    __syncthreads();
    if (qid == 0 && wn == 0) {
        #pragma unroll
        for (int mi = 0; mi < 2; mi++)
            #pragma unroll
            for (int h = 0; h < 2; h++)
                if (mi < MI) {
                    const int r = wm*rowBand + mi*16 + gid + h*8;
                    g_att[row0 + r] = p[mi][h] + s_half[128 + r]
                                    + s_half[256 + r] + s_half[384 + r];
                }
    }
}

// ---------------------------------------------------------------------------
// softmax + coverage: separate kernel (proven)
// ---------------------------------------------------------------------------
__global__ __launch_bounds__(512) void softmax_kernel(
    const int* __restrict__ lens,
    const float* __restrict__ cov,
    float* __restrict__ out)
{
    __shared__ float red[17];
    const int b = blockIdx.x;
    const int tid = threadIdx.x;
    const int len = lens[b];
    const float NEG_INF = __int_as_float(0xff800000);

    float v[4];
    float mx = NEG_INF;
    #pragma unroll
    for (int j = 0; j < 4; j++) {
        const int i = tid + j*512;
        float x = (i < len) ? g_att[b*Ss + i] : NEG_INF;
        v[j] = x;
        mx = fmaxf(mx, x);
    }
    #pragma unroll
    for (int m = 16; m >= 1; m >>= 1)
        mx = fmaxf(mx, __shfl_xor_sync(0xffffffffu, mx, m));
    if ((tid & 31) == 0) red[tid >> 5] = mx;
    __syncthreads();
    if (tid == 0) {
        float m = red[0];
        #pragma unroll
        for (int i = 1; i < 16; i++) m = fmaxf(m, red[i]);
        red[16] = m;
    }
    __syncthreads();
    mx = red[16];

    float sum = 0.f;
    #pragma unroll
    for (int j = 0; j < 4; j++) {
        float e = __expf(v[j] - mx);
        v[j] = e;
        sum += e;
    }
    #pragma unroll
    for (int m = 16; m >= 1; m >>= 1)
        sum += __shfl_xor_sync(0xffffffffu, sum, m);
    __syncthreads();
    if ((tid & 31) == 0) red[tid >> 5] = sum;
    __syncthreads();
    if (tid == 0) {
        float t = 0.f;
        #pragma unroll
        for (int i = 0; i < 16; i++) t += red[i];
        red[16] = t;
    }
    __syncthreads();
    const float inv = __fdividef(1.0f, red[16]);

    #pragma unroll
    for (int j = 0; j < 4; j++) {
        const int i = tid + j*512;
        const float w = v[j] * inv;
        out[b*Ss + i] = w;
        out[NROWS + b*Ss + i] = cov[b*Ss + i] + w;
    }
}

// ---------------------------------------------------------------------------
extern "C" void kernel_launch(void* const* d_in, const int* in_sizes, int n_in,
                              void* d_out, int out_size) {
    const float* dec_input = (const float*)d_in[0];
    const float* enc       = (const float*)d_in[1];
    const int*   lens      = (const int*)  d_in[2];
    const float* cov       = (const float*)d_in[3];
    const float* W         = (const float*)d_in[4];
    const float* bias      = (const float*)d_in[5];
    const float* v_w       = (const float*)d_in[6];
    float* out = (float*)d_out;

    static int configured = 0;
    if (!configured) {
        cudaFuncSetAttribute(gemm_kernel,
                             cudaFuncAttributeMaxDynamicSharedMemorySize, SMEM_DYN);
        configured = 1;
    }

    prep_kernel<<<528, 256>>>(dec_input, W);

    // gemm with Programmatic Dependent Launch: prologue overlaps prep
    {
        cudaLaunchConfig_t cfg = {};
        cfg.gridDim = dim3(NFULL + NHALF, 1, 1);
        cfg.blockDim = dim3(512, 1, 1);
        cfg.dynamicSmemBytes = SMEM_DYN;
        cfg.stream = 0;
        cudaLaunchAttribute attr[1];
        attr[0].id = cudaLaunchAttributeProgrammaticStreamSerialization;
        attr[0].val.programmaticStreamSerializationAllowed = 1;
        cfg.attrs = attr;
        cfg.numAttrs = 1;
        cudaLaunchKernelEx(&cfg, gemm_kernel, enc, cov, v_w, bias);
    }

    softmax_kernel<<<Bb, 512>>>(lens, cov, out);
}